// round 2
// baseline (speedup 1.0000x reference)
#include <cuda_runtime.h>
#include <math.h>

// Spectral Mixture kernel, N=M=4096, D=4, Q=4.
// out[n,m] = sum_q w_q * exp(-2pi^2 sum_d tau_d^2 v_qd) * prod_d cos(2pi tau_d mu_qd),
//            tau = x[n] - y[m].
//
// Separable formulation:
//   cos(2pi mu (x-y)) = cos(a)cos(b) + sin(a)sin(b),  a = 2pi mu x, b = 2pi mu y
//   exponent (base 2):  ea = pn(n,q) + pm(m,q) + sum_d w(n,q,d) * y(m,d)
//     pn = lw*log2e - c2*sum_d v x^2,  pm = -c2*sum_d v y^2,  w = 2*c2*v*x,
//     c2 = 2*pi^2*log2e;  term = ex2(ea).
// Only 4 MUFU ex2 per element; all cos handled by FMA reconstruction.
// n-dimension packed pairwise into f32x2 (FFMA2) -> ~34 packed FMA ops/elem.
// n-side pack precomputed to global, staged in smem, read as uniform broadcast.
// m-side pack computed on the fly, held duplicated in registers.

#define NSIZE 4096
#define MSIZE 4096
#define NPAIRS (NSIZE / 2)
#define PN_STRIDE 52          // float2 entries per n-pair: pn[4], w[16], ca[16], sa[16]
#define TILE_NPAIRS 32        // n-pairs per block (64 n rows)

__device__ float2 g_PN2[NPAIRS * PN_STRIDE];   // ~852 KB

// ---------- f32x2 helpers ----------
struct f2 { unsigned long long v; };

__device__ __forceinline__ f2 pack2(float lo, float hi) {
    f2 r; asm("mov.b64 %0, {%1, %2};" : "=l"(r.v) : "f"(lo), "f"(hi)); return r;
}
__device__ __forceinline__ f2 dup2(float x) { return pack2(x, x); }
__device__ __forceinline__ void unpack2(f2 a, float& lo, float& hi) {
    asm("mov.b64 {%0, %1}, %2;" : "=f"(lo), "=f"(hi) : "l"(a.v));
}
__device__ __forceinline__ f2 fma2(f2 a, f2 b, f2 c) {
    f2 r; asm("fma.rn.f32x2 %0, %1, %2, %3;" : "=l"(r.v) : "l"(a.v), "l"(b.v), "l"(c.v)); return r;
}
__device__ __forceinline__ f2 mul2(f2 a, f2 b) {
    f2 r; asm("mul.rn.f32x2 %0, %1, %2;" : "=l"(r.v) : "l"(a.v), "l"(b.v)); return r;
}
__device__ __forceinline__ f2 add2(f2 a, f2 b) {
    f2 r; asm("add.rn.f32x2 %0, %1, %2;" : "=l"(r.v) : "l"(a.v), "l"(b.v)); return r;
}
__device__ __forceinline__ float ex2f(float x) {
    float r; asm("ex2.approx.ftz.f32 %0, %1;" : "=f"(r) : "f"(x)); return r;
}

#define SM_LOG2E 1.4426950408889634f
#define SM_TWOPI 6.2831853071795865f
#define SM_C2    28.476607895483232f   // 2*pi^2*log2(e)

// ---------- per-n pack precompute ----------
__global__ void sm_prep_n(const float* __restrict__ x,
                          const float* __restrict__ lw,
                          const float* __restrict__ mu,
                          const float* __restrict__ lv) {
    int n = blockIdx.x * blockDim.x + threadIdx.x;
    if (n >= NSIZE) return;
    float xd[4];
#pragma unroll
    for (int d = 0; d < 4; d++) xd[d] = x[n * 4 + d];

    int pair = n >> 1;
    int half = n & 1;
    float* base = (float*)&g_PN2[pair * PN_STRIDE];  // interleaved float2 components

#pragma unroll
    for (int q = 0; q < 4; q++) {
        float pn = lw[q] * SM_LOG2E;
#pragma unroll
        for (int d = 0; d < 4; d++) {
            float v = SM_C2 * __expf(lv[q * 4 + d]);       // c2 * variance
            pn -= v * xd[d] * xd[d];
            base[(4 + q * 4 + d) * 2 + half] = 2.0f * v * xd[d];   // w
            float a = SM_TWOPI * mu[q * 4 + d] * xd[d];
            float s, c;
            sincosf(a, &s, &c);                             // accurate (off hot path)
            base[(20 + q * 4 + d) * 2 + half] = c;          // ca
            base[(36 + q * 4 + d) * 2 + half] = s;          // sa
        }
        base[q * 2 + half] = pn;                            // pn
    }
}

// ---------- main kernel ----------
__global__ __launch_bounds__(256, 2) void sm_main(
    const float* __restrict__ y,
    const float* __restrict__ mu,
    const float* __restrict__ lv,
    float* __restrict__ out) {

    __shared__ float2 tile[TILE_NPAIRS * PN_STRIDE];   // 13312 B

    int tid = threadIdx.x;
    int m = blockIdx.x * 256 + tid;          // one m per thread
    int pbase = blockIdx.y * TILE_NPAIRS;    // first n-pair of this block

    // cooperative load of this block's n-pack tile
    {
        const float2* src = g_PN2 + pbase * PN_STRIDE;
#pragma unroll 4
        for (int i = tid; i < TILE_NPAIRS * PN_STRIDE; i += 256)
            tile[i] = src[i];
    }

    // ---- m-side prep (registers, duplicated into both f32x2 halves) ----
    float4 yv = ((const float4*)y)[m];
    float yd[4] = {yv.x, yv.y, yv.z, yv.w};
    f2 y2[4];
#pragma unroll
    for (int d = 0; d < 4; d++) y2[d] = dup2(yd[d]);

    f2 cb2[16], sb2[16], pm2[4];
#pragma unroll
    for (int q = 0; q < 4; q++) {
        float pm = 0.0f;
#pragma unroll
        for (int d = 0; d < 4; d++) {
            float v = SM_C2 * __expf(lv[q * 4 + d]);
            pm -= v * yd[d] * yd[d];
            float b = SM_TWOPI * mu[q * 4 + d] * yd[d];
            cb2[q * 4 + d] = dup2(__cosf(b));
            sb2[q * 4 + d] = dup2(__sinf(b));
        }
        pm2[q] = dup2(pm);
    }

    __syncthreads();

    const unsigned long long* tl = (const unsigned long long*)tile;

#pragma unroll 2
    for (int np = 0; np < TILE_NPAIRS; np++) {
        const unsigned long long* t = tl + np * PN_STRIDE;  // uniform -> broadcast LDS
        f2 acc; acc.v = 0ULL;

#pragma unroll
        for (int q = 0; q < 4; q++) {
            // exponent: pn + pm + sum_d w*y
            f2 pn2; pn2.v = t[q];
            f2 ea = add2(pn2, pm2[q]);
#pragma unroll
            for (int d = 0; d < 4; d++) {
                f2 w2; w2.v = t[4 + q * 4 + d];
                ea = fma2(w2, y2[d], ea);
            }
            float elo, ehi;
            unpack2(ea, elo, ehi);
            f2 e2 = pack2(ex2f(elo), ex2f(ehi));   // w_q * exp(-2pi^2 sum tau^2 v)

            // cos product via cos(a-b) = ca*cb + sa*sb
            f2 cc0, cc1, cc2c, cc3;
            {
                f2 ca, sa;
                ca.v = t[20 + q * 4 + 0]; sa.v = t[36 + q * 4 + 0];
                cc0 = fma2(sa, sb2[q * 4 + 0], mul2(ca, cb2[q * 4 + 0]));
                ca.v = t[20 + q * 4 + 1]; sa.v = t[36 + q * 4 + 1];
                cc1 = fma2(sa, sb2[q * 4 + 1], mul2(ca, cb2[q * 4 + 1]));
                ca.v = t[20 + q * 4 + 2]; sa.v = t[36 + q * 4 + 2];
                cc2c = fma2(sa, sb2[q * 4 + 2], mul2(ca, cb2[q * 4 + 2]));
                ca.v = t[20 + q * 4 + 3]; sa.v = t[36 + q * 4 + 3];
                cc3 = fma2(sa, sb2[q * 4 + 3], mul2(ca, cb2[q * 4 + 3]));
            }
            f2 prod = mul2(mul2(cc0, cc1), mul2(cc2c, cc3));
            acc = fma2(e2, prod, acc);
        }

        float alo, ahi;
        unpack2(acc, alo, ahi);
        int n0 = (pbase + np) * 2;
        out[(long)n0 * MSIZE + m] = alo;           // row n0  (coalesced across warp)
        out[((long)n0 + 1) * MSIZE + m] = ahi;     // row n0+1
    }
}

extern "C" void kernel_launch(void* const* d_in, const int* in_sizes, int n_in,
                              void* d_out, int out_size) {
    const float* x  = (const float*)d_in[0];
    const float* y  = (const float*)d_in[1];
    const float* lw = (const float*)d_in[2];
    const float* mu = (const float*)d_in[3];
    const float* lv = (const float*)d_in[4];
    float* out = (float*)d_out;

    sm_prep_n<<<16, 256>>>(x, lw, mu, lv);

    dim3 grid(MSIZE / 256, NPAIRS / TILE_NPAIRS);   // (16, 64)
    sm_main<<<grid, 256>>>(y, mu, lv, out);
}

// round 7
// speedup vs baseline: 1.2057x; 1.2057x over previous
#include <cuda_runtime.h>
#include <math.h>

// Spectral Mixture kernel, N=M=4096, D=4, Q=4 — separable form, f32x2 over n-pairs.
//   cos(2pi mu (x-y)) = ca*cb + sa*sb       (a = 2pi mu x, b = 2pi mu y)
//   base-2 exponent:  ea = pn(n,q) + pm(m,q) + sum_d w(n,q,d)*y(m,d);  term = ex2(ea)
// R4..R7: 2 m-columns per thread + LDS.128 (ulonglong2) n-pack loads + bounded unroll.

#define NSIZE 4096
#define MSIZE 4096
#define NPAIRS (NSIZE / 2)
#define PN_STRIDE 52          // float2 per n-pair: pn[4], w[16], ca[16], sa[16]
#define TILE_NPAIRS 32        // n-pairs per block (64 n rows)

__device__ float2 g_PN2[NPAIRS * PN_STRIDE];

// ---------- f32x2 helpers ----------
struct f2 { unsigned long long v; };

__device__ __forceinline__ f2 pack2(float lo, float hi) {
    f2 r; asm("mov.b64 %0, {%1, %2};" : "=l"(r.v) : "f"(lo), "f"(hi)); return r;
}
__device__ __forceinline__ f2 dup2(float x) { return pack2(x, x); }
__device__ __forceinline__ void unpack2(f2 a, float& lo, float& hi) {
    asm("mov.b64 {%0, %1}, %2;" : "=f"(lo), "=f"(hi) : "l"(a.v));
}
__device__ __forceinline__ f2 fma2(f2 a, f2 b, f2 c) {
    f2 r; asm("fma.rn.f32x2 %0, %1, %2, %3;" : "=l"(r.v) : "l"(a.v), "l"(b.v), "l"(c.v)); return r;
}
__device__ __forceinline__ f2 mul2(f2 a, f2 b) {
    f2 r; asm("mul.rn.f32x2 %0, %1, %2;" : "=l"(r.v) : "l"(a.v), "l"(b.v)); return r;
}
__device__ __forceinline__ f2 add2(f2 a, f2 b) {
    f2 r; asm("add.rn.f32x2 %0, %1, %2;" : "=l"(r.v) : "l"(a.v), "l"(b.v)); return r;
}
__device__ __forceinline__ float ex2f(float x) {
    float r; asm("ex2.approx.ftz.f32 %0, %1;" : "=f"(r) : "f"(x)); return r;
}

#define SM_LOG2E 1.4426950408889634f
#define SM_TWOPI 6.2831853071795865f
#define SM_C2    28.476607895483232f   // 2*pi^2*log2(e)

// ---------- per-n pack precompute ----------
__global__ void sm_prep_n(const float* __restrict__ x,
                          const float* __restrict__ lw,
                          const float* __restrict__ mu,
                          const float* __restrict__ lv) {
    int n = blockIdx.x * blockDim.x + threadIdx.x;
    if (n >= NSIZE) return;
    float xd[4];
#pragma unroll
    for (int d = 0; d < 4; d++) xd[d] = x[n * 4 + d];

    int pair = n >> 1;
    int half = n & 1;
    float* base = (float*)&g_PN2[pair * PN_STRIDE];

#pragma unroll
    for (int q = 0; q < 4; q++) {
        float pn = lw[q] * SM_LOG2E;
#pragma unroll
        for (int d = 0; d < 4; d++) {
            float v = SM_C2 * __expf(lv[q * 4 + d]);
            pn -= v * xd[d] * xd[d];
            base[(4 + q * 4 + d) * 2 + half] = 2.0f * v * xd[d];
            float a = SM_TWOPI * mu[q * 4 + d] * xd[d];
            float s, c;
            sincosf(a, &s, &c);
            base[(20 + q * 4 + d) * 2 + half] = c;
            base[(36 + q * 4 + d) * 2 + half] = s;
        }
        base[q * 2 + half] = pn;
    }
}

// ---------- main kernel: 128 threads, 2 m-columns per thread ----------
__global__ __launch_bounds__(128, 2) void sm_main(
    const float* __restrict__ y,
    const float* __restrict__ mu,
    const float* __restrict__ lv,
    float* __restrict__ out) {

    __shared__ __align__(16) float2 tile[TILE_NPAIRS * PN_STRIDE];   // 13312 B

    int tid = threadIdx.x;
    int mcol0 = blockIdx.x * 256;            // block covers 256 m columns
    int pbase = blockIdx.y * TILE_NPAIRS;

    // cooperative tile load
    {
        const float2* src = g_PN2 + pbase * PN_STRIDE;
#pragma unroll
        for (int i = 0; i < 13; i++)
            tile[i * 128 + tid] = src[i * 128 + tid];
    }

    // ---- m-side prep for the thread's two columns ----
    int mm[2];
    mm[0] = mcol0 + tid;
    mm[1] = mcol0 + tid + 128;

    f2 ym[2][4], pmm[2][4], cbm[2][16], sbm[2][16];
#pragma unroll
    for (int i = 0; i < 2; i++) {
        float4 yv = ((const float4*)y)[mm[i]];
        float yd[4] = {yv.x, yv.y, yv.z, yv.w};
#pragma unroll
        for (int d = 0; d < 4; d++) ym[i][d] = dup2(yd[d]);
#pragma unroll
        for (int q = 0; q < 4; q++) {
            float pm = 0.0f;
#pragma unroll
            for (int d = 0; d < 4; d++) {
                float v = SM_C2 * __expf(lv[q * 4 + d]);
                pm -= v * yd[d] * yd[d];
                float b = SM_TWOPI * mu[q * 4 + d] * yd[d];
                cbm[i][q * 4 + d] = dup2(__cosf(b));
                sbm[i][q * 4 + d] = dup2(__sinf(b));
            }
            pmm[i][q] = dup2(pm);
        }
    }

    __syncthreads();

#pragma unroll 2
    for (int np = 0; np < TILE_NPAIRS; np++) {
        // warp-uniform base -> broadcast LDS.128
        const ulonglong2* t4 = (const ulonglong2*)(tile + np * PN_STRIDE);

        // pn quad (4 f2) via 2 LDS.128
        ulonglong2 pnA = t4[0];
        ulonglong2 pnB = t4[1];
        f2 pnq[4];
        pnq[0].v = pnA.x; pnq[1].v = pnA.y; pnq[2].v = pnB.x; pnq[3].v = pnB.y;

        f2 acc0; acc0.v = 0ULL;
        f2 acc1; acc1.v = 0ULL;

#pragma unroll
        for (int q = 0; q < 4; q++) {
            ulonglong2 wA  = t4[2 + 2 * q],  wB  = t4[3 + 2 * q];
            ulonglong2 caA = t4[10 + 2 * q], caB = t4[11 + 2 * q];
            ulonglong2 saA = t4[18 + 2 * q], saB = t4[19 + 2 * q];
            f2 w2[4], ca2[4], sa2[4];
            w2[0].v = wA.x;  w2[1].v = wA.y;  w2[2].v = wB.x;  w2[3].v = wB.y;
            ca2[0].v = caA.x; ca2[1].v = caA.y; ca2[2].v = caB.x; ca2[3].v = caB.y;
            sa2[0].v = saA.x; sa2[1].v = saA.y; sa2[2].v = saB.x; sa2[3].v = saB.y;

            // --- m column 0 ---
            {
                f2 ea = add2(pnq[q], pmm[0][q]);
#pragma unroll
                for (int d = 0; d < 4; d++) ea = fma2(w2[d], ym[0][d], ea);
                float elo, ehi; unpack2(ea, elo, ehi);
                f2 e2 = pack2(ex2f(elo), ex2f(ehi));

                f2 c0 = fma2(sa2[0], sbm[0][q * 4 + 0], mul2(ca2[0], cbm[0][q * 4 + 0]));
                f2 c1 = fma2(sa2[1], sbm[0][q * 4 + 1], mul2(ca2[1], cbm[0][q * 4 + 1]));
                f2 c2 = fma2(sa2[2], sbm[0][q * 4 + 2], mul2(ca2[2], cbm[0][q * 4 + 2]));
                f2 c3 = fma2(sa2[3], sbm[0][q * 4 + 3], mul2(ca2[3], cbm[0][q * 4 + 3]));
                f2 prod = mul2(mul2(c0, c1), mul2(c2, c3));
                acc0 = fma2(e2, prod, acc0);
            }
            // --- m column 1 ---
            {
                f2 ea = add2(pnq[q], pmm[1][q]);
#pragma unroll
                for (int d = 0; d < 4; d++) ea = fma2(w2[d], ym[1][d], ea);
                float elo, ehi; unpack2(ea, elo, ehi);
                f2 e2 = pack2(ex2f(elo), ex2f(ehi));

                f2 c0 = fma2(sa2[0], sbm[1][q * 4 + 0], mul2(ca2[0], cbm[1][q * 4 + 0]));
                f2 c1 = fma2(sa2[1], sbm[1][q * 4 + 1], mul2(ca2[1], cbm[1][q * 4 + 1]));
                f2 c2 = fma2(sa2[2], sbm[1][q * 4 + 2], mul2(ca2[2], cbm[1][q * 4 + 2]));
                f2 c3 = fma2(sa2[3], sbm[1][q * 4 + 3], mul2(ca2[3], cbm[1][q * 4 + 3]));
                f2 prod = mul2(mul2(c0, c1), mul2(c2, c3));
                acc1 = fma2(e2, prod, acc1);
            }
        }

        int n0 = (pbase + np) * 2;
        float a, b;
        unpack2(acc0, a, b);
        out[(long)n0 * MSIZE + mm[0]]       = a;
        out[((long)n0 + 1) * MSIZE + mm[0]] = b;
        unpack2(acc1, a, b);
        out[(long)n0 * MSIZE + mm[1]]       = a;
        out[((long)n0 + 1) * MSIZE + mm[1]] = b;
    }
}

extern "C" void kernel_launch(void* const* d_in, const int* in_sizes, int n_in,
                              void* d_out, int out_size) {
    const float* x  = (const float*)d_in[0];
    const float* y  = (const float*)d_in[1];
    const float* lw = (const float*)d_in[2];
    const float* mu = (const float*)d_in[3];
    const float* lv = (const float*)d_in[4];
    float* out = (float*)d_out;

    sm_prep_n<<<16, 256>>>(x, lw, mu, lv);

    dim3 grid(MSIZE / 256, NPAIRS / TILE_NPAIRS);   // (16, 64)
    sm_main<<<grid, 128>>>(y, mu, lv, out);
}